// round 3
// baseline (speedup 1.0000x reference)
#include <cuda_runtime.h>
#include <cuda_bf16.h>
#include <math.h>

// ---------------------------------------------------------------------------
// Problem constants
// ---------------------------------------------------------------------------
#define B 8
#define SEQ 1024
#define NROW 32
#define NCOL 32
#define WIN 9
#define D 512
#define DFF 1024
#define VOCAB 16384
#define NTOK (B * SEQ)   // 8192
#define EPS 1e-5f

// ---------------------------------------------------------------------------
// Scratch buffers (device globals: no allocation allowed)
// ---------------------------------------------------------------------------
__device__ float g_h0 [NTOK * D];    // embed + pos
__device__ float g_q  [NTOK * D];
__device__ float g_k  [NTOK * D];
__device__ float g_v  [NTOK * D];
__device__ float g_att[NTOK * D];    // attention output (pre O-proj)
__device__ float g_o  [NTOK * D];    // O-proj output
__device__ float g_h1 [NTOK * D];    // after LN1
__device__ float g_mid[NTOK * DFF];  // FFN hidden
__device__ float g_f  [NTOK * D];    // FFN output
__device__ float g_h2 [NTOK * D];    // after LN2

// ---------------------------------------------------------------------------
// Kernel 1: embedding gather + 2D positional encoding
// h0[b,s,:] = embed_tab[x[b,s],:] + [row_embed[s/32,:], col_embed[s%32,:]]
// one block (128 thr) per token row; float4 vectorized
// ---------------------------------------------------------------------------
__global__ void embed_kernel(const int* __restrict__ x,
                             const float* __restrict__ tab,
                             const float* __restrict__ rowe,
                             const float* __restrict__ cole,
                             float* __restrict__ h) {
    int qi = blockIdx.x;             // 0..8191
    int s  = qi & (SEQ - 1);
    int r  = s >> 5, c = s & 31;
    int tok = x[qi];
    int d = threadIdx.x * 4;

    float4 e = *(const float4*)&tab[(size_t)tok * D + d];
    float4 p;
    if (d < D / 2) p = *(const float4*)&rowe[r * (D / 2) + d];
    else           p = *(const float4*)&cole[c * (D / 2) + (d - D / 2)];
    e.x += p.x; e.y += p.y; e.z += p.z; e.w += p.w;
    *(float4*)&h[(size_t)qi * D + d] = e;
}

// ---------------------------------------------------------------------------
// Kernel 2: generic fp32 GEMM + bias (+ optional ReLU)
//   C[M,N] = A[M,K] @ B[K,N] + bias[N]
// 128x128 tile, BK=8, 256 threads, 8x8 per thread.
// All M,N multiples of 128; K multiple of 8 (holds for every call here).
// ---------------------------------------------------------------------------
__global__ void gemm_bias(const float* __restrict__ A,
                          const float* __restrict__ Bm,
                          const float* __restrict__ bias,
                          float* __restrict__ C,
                          int M, int N, int K, int relu) {
    __shared__ float As[8][128];
    __shared__ float Bs[8][128];

    int tid = threadIdx.x;
    int bm = blockIdx.y * 128;
    int bn = blockIdx.x * 128;

    int arow = tid >> 1;             // 0..127
    int acol = (tid & 1) * 4;        // 0 or 4
    int brow = tid >> 5;             // 0..7
    int bcol = (tid & 31) * 4;       // 0..124

    int ty = tid >> 4;               // 0..15
    int tx = tid & 15;               // 0..15

    float acc[8][8];
#pragma unroll
    for (int i = 0; i < 8; i++)
#pragma unroll
        for (int j = 0; j < 8; j++) acc[i][j] = 0.0f;

    for (int k0 = 0; k0 < K; k0 += 8) {
        float4 av = *(const float4*)&A[(size_t)(bm + arow) * K + k0 + acol];
        As[acol + 0][arow] = av.x;
        As[acol + 1][arow] = av.y;
        As[acol + 2][arow] = av.z;
        As[acol + 3][arow] = av.w;
        float4 bv = *(const float4*)&Bm[(size_t)(k0 + brow) * N + bn + bcol];
        *(float4*)&Bs[brow][bcol] = bv;
        __syncthreads();

#pragma unroll
        for (int kk = 0; kk < 8; kk++) {
            float a[8], bb[8];
#pragma unroll
            for (int i = 0; i < 8; i++) a[i] = As[kk][ty * 8 + i];
#pragma unroll
            for (int j = 0; j < 8; j++) bb[j] = Bs[kk][tx * 8 + j];
#pragma unroll
            for (int i = 0; i < 8; i++)
#pragma unroll
                for (int j = 0; j < 8; j++) acc[i][j] = fmaf(a[i], bb[j], acc[i][j]);
        }
        __syncthreads();
    }

#pragma unroll
    for (int i = 0; i < 8; i++) {
        int row = bm + ty * 8 + i;
#pragma unroll
        for (int j = 0; j < 8; j += 4) {
            int col = bn + tx * 8 + j;
            float4 o;
            o.x = acc[i][j + 0] + bias[col + 0];
            o.y = acc[i][j + 1] + bias[col + 1];
            o.z = acc[i][j + 2] + bias[col + 2];
            o.w = acc[i][j + 3] + bias[col + 3];
            if (relu) {
                o.x = fmaxf(o.x, 0.0f); o.y = fmaxf(o.y, 0.0f);
                o.z = fmaxf(o.z, 0.0f); o.w = fmaxf(o.w, 0.0f);
            }
            *(float4*)&C[(size_t)row * N + col] = o;
        }
    }
}

// ---------------------------------------------------------------------------
// Kernel 3: fused local-causal attention.
// One block (128 thr) per query token. Allowed keys: rows r-9..r, cols c-9..c+9,
// row r truncated at col c (causal). <= 181 keys.
// ---------------------------------------------------------------------------
__global__ void attn_kernel(const float* __restrict__ Q,
                            const float* __restrict__ K,
                            const float* __restrict__ V,
                            float* __restrict__ O) {
    int qi = blockIdx.x;
    int b = qi >> 10, s = qi & (SEQ - 1);
    int r = s >> 5, c = s & 31;
    int r0 = (r - WIN < 0) ? 0 : r - WIN;
    int c0 = (c - WIN < 0) ? 0 : c - WIN;
    int c1 = (c + WIN > 31) ? 31 : c + WIN;
    int wcols = c1 - c0 + 1;
    int nfull = r - r0;
    int nk = nfull * wcols + (c - c0 + 1);

    __shared__ float qv[D];
    __shared__ float sc[256];
    __shared__ int   kid[256];
    __shared__ float red[4];

    int tid = threadIdx.x;
    int lane = tid & 31, wid = tid >> 5;

    // load q row
    *(float4*)&qv[tid * 4] = *(const float4*)&Q[(size_t)qi * D + tid * 4];
    __syncthreads();

    const float scale = 0.044194173824159216f;  // 1/sqrt(512)
    const float* kbase = K + (size_t)b * SEQ * D;

    // scores: warp w handles keys w, w+4, ...
    for (int j = wid; j < nk; j += 4) {
        int row, col;
        if (j < nfull * wcols) { row = r0 + j / wcols; col = c0 + j % wcols; }
        else                   { row = r;             col = c0 + (j - nfull * wcols); }
        int kk = row * 32 + col;
        const float* krow = kbase + (size_t)kk * D;
        float sum = 0.0f;
#pragma unroll
        for (int t = 0; t < D / 32; t++)
            sum = fmaf(qv[lane + 32 * t], krow[lane + 32 * t], sum);
#pragma unroll
        for (int off = 16; off; off >>= 1)
            sum += __shfl_xor_sync(0xffffffffu, sum, off);
        if (lane == 0) { sc[j] = sum * scale; kid[j] = kk; }
    }
    __syncthreads();

    // block max
    float m = -1e30f;
    for (int j = tid; j < nk; j += 128) m = fmaxf(m, sc[j]);
#pragma unroll
    for (int off = 16; off; off >>= 1)
        m = fmaxf(m, __shfl_xor_sync(0xffffffffu, m, off));
    if (lane == 0) red[wid] = m;
    __syncthreads();
    m = fmaxf(fmaxf(red[0], red[1]), fmaxf(red[2], red[3]));

    // exp + sum
    float ssum = 0.0f;
    for (int j = tid; j < nk; j += 128) {
        float e = __expf(sc[j] - m);
        sc[j] = e;
        ssum += e;
    }
    __syncthreads();   // covers red reuse + sc writes
#pragma unroll
    for (int off = 16; off; off >>= 1)
        ssum += __shfl_xor_sync(0xffffffffu, ssum, off);
    if (lane == 0) red[wid] = ssum;
    __syncthreads();
    float inv = 1.0f / (red[0] + red[1] + red[2] + red[3]);

    // weighted sum of V rows: thread t owns dims [4t, 4t+4)
    const float* vbase = V + (size_t)b * SEQ * D;
    int d = tid * 4;
    float4 acc = make_float4(0.f, 0.f, 0.f, 0.f);
    for (int j = 0; j < nk; j++) {
        float w = sc[j] * inv;
        float4 v = *(const float4*)&vbase[(size_t)kid[j] * D + d];
        acc.x = fmaf(w, v.x, acc.x);
        acc.y = fmaf(w, v.y, acc.y);
        acc.z = fmaf(w, v.z, acc.z);
        acc.w = fmaf(w, v.w, acc.w);
    }
    *(float4*)&O[(size_t)qi * D + d] = acc;
}

// ---------------------------------------------------------------------------
// Kernel 4: out = LayerNorm(X + Y) * g + b   (row-wise over D=512)
// One block (128 thr) per row.
// ---------------------------------------------------------------------------
__global__ void add_ln_kernel(const float* __restrict__ X,
                              const float* __restrict__ Y,
                              const float* __restrict__ g,
                              const float* __restrict__ beta,
                              float* __restrict__ out) {
    int row = blockIdx.x;
    int tid = threadIdx.x;
    int lane = tid & 31, wid = tid >> 5;
    __shared__ float reds[4], redq[4];

    int d = tid * 4;
    float4 xv = *(const float4*)&X[(size_t)row * D + d];
    float4 yv = *(const float4*)&Y[(size_t)row * D + d];
    xv.x += yv.x; xv.y += yv.y; xv.z += yv.z; xv.w += yv.w;

    float s  = xv.x + xv.y + xv.z + xv.w;
    float sq = xv.x * xv.x + xv.y * xv.y + xv.z * xv.z + xv.w * xv.w;
#pragma unroll
    for (int off = 16; off; off >>= 1) {
        s  += __shfl_xor_sync(0xffffffffu, s,  off);
        sq += __shfl_xor_sync(0xffffffffu, sq, off);
    }
    if (lane == 0) { reds[wid] = s; redq[wid] = sq; }
    __syncthreads();
    s  = reds[0] + reds[1] + reds[2] + reds[3];
    sq = redq[0] + redq[1] + redq[2] + redq[3];

    float mu  = s * (1.0f / D);
    float var = sq * (1.0f / D) - mu * mu;
    float rstd = rsqrtf(var + EPS);

    float4 gv = *(const float4*)&g[d];
    float4 bv = *(const float4*)&beta[d];
    float4 o;
    o.x = (xv.x - mu) * rstd * gv.x + bv.x;
    o.y = (xv.y - mu) * rstd * gv.y + bv.y;
    o.z = (xv.z - mu) * rstd * gv.z + bv.z;
    o.w = (xv.w - mu) * rstd * gv.w + bv.w;
    *(float4*)&out[(size_t)row * D + d] = o;
}

// ---------------------------------------------------------------------------
// Launch
// ---------------------------------------------------------------------------
extern "C" void kernel_launch(void* const* d_in, const int* in_sizes, int n_in,
                              void* d_out, int out_size) {
    const int*   x     = (const int*)  d_in[0];
    const float* tab   = (const float*)d_in[1];
    const float* rowe  = (const float*)d_in[2];
    const float* cole  = (const float*)d_in[3];
    const float* Wq    = (const float*)d_in[4];
    const float* bq    = (const float*)d_in[5];
    const float* Wk    = (const float*)d_in[6];
    const float* bk    = (const float*)d_in[7];
    const float* Wv    = (const float*)d_in[8];
    const float* bv    = (const float*)d_in[9];
    const float* Wo    = (const float*)d_in[10];
    const float* bo    = (const float*)d_in[11];
    const float* ln1g  = (const float*)d_in[12];
    const float* ln1b  = (const float*)d_in[13];
    const float* W1    = (const float*)d_in[14];
    const float* b1    = (const float*)d_in[15];
    const float* W2    = (const float*)d_in[16];
    const float* b2    = (const float*)d_in[17];
    const float* ln2g  = (const float*)d_in[18];
    const float* ln2b  = (const float*)d_in[19];
    const float* Wh    = (const float*)d_in[20];
    const float* bh    = (const float*)d_in[21];
    float* out = (float*)d_out;

    float *h0, *q, *k, *v, *att, *o, *h1, *mid, *f, *h2;
    cudaGetSymbolAddress((void**)&h0,  g_h0);
    cudaGetSymbolAddress((void**)&q,   g_q);
    cudaGetSymbolAddress((void**)&k,   g_k);
    cudaGetSymbolAddress((void**)&v,   g_v);
    cudaGetSymbolAddress((void**)&att, g_att);
    cudaGetSymbolAddress((void**)&o,   g_o);
    cudaGetSymbolAddress((void**)&h1,  g_h1);
    cudaGetSymbolAddress((void**)&mid, g_mid);
    cudaGetSymbolAddress((void**)&f,   g_f);
    cudaGetSymbolAddress((void**)&h2,  g_h2);

    // 1. embedding + pos
    embed_kernel<<<NTOK, 128>>>(x, tab, rowe, cole, h0);

    // 2. Q,K,V projections
    gemm_bias<<<dim3(D / 128, NTOK / 128), 256>>>(h0, Wq, bq, q, NTOK, D, D, 0);
    gemm_bias<<<dim3(D / 128, NTOK / 128), 256>>>(h0, Wk, bk, k, NTOK, D, D, 0);
    gemm_bias<<<dim3(D / 128, NTOK / 128), 256>>>(h0, Wv, bv, v, NTOK, D, D, 0);

    // 3. fused local-causal attention
    attn_kernel<<<NTOK, 128>>>(q, k, v, att);

    // 4. output projection
    gemm_bias<<<dim3(D / 128, NTOK / 128), 256>>>(att, Wo, bo, o, NTOK, D, D, 0);

    // 5. residual + LN1
    add_ln_kernel<<<NTOK, 128>>>(h0, o, ln1g, ln1b, h1);

    // 6. FFN
    gemm_bias<<<dim3(DFF / 128, NTOK / 128), 256>>>(h1, W1, b1, mid, NTOK, DFF, D, 1);
    gemm_bias<<<dim3(D / 128, NTOK / 128), 256>>>(mid, W2, b2, f, NTOK, D, DFF, 0);

    // 7. residual + LN2
    add_ln_kernel<<<NTOK, 128>>>(h1, f, ln2g, ln2b, h2);

    // 8. vocab head -> d_out
    gemm_bias<<<dim3(VOCAB / 128, NTOK / 128), 256>>>(h2, Wh, bh, out, NTOK, VOCAB, D, 0);
}

// round 5
// speedup vs baseline: 4.4396x; 4.4396x over previous
#include <cuda_runtime.h>
#include <cuda_bf16.h>
#include <math.h>
#include <cstdint>

// ---------------------------------------------------------------------------
// Problem constants
// ---------------------------------------------------------------------------
#define B 8
#define SEQ 1024
#define WIN 9
#define D 512
#define DFF 1024
#define VOCAB 16384
#define NTOK (B * SEQ)   // 8192
#define EPS 1e-5f

// ---------------------------------------------------------------------------
// Scratch buffers (device globals: no allocation allowed)
// ---------------------------------------------------------------------------
__device__ float g_h0 [NTOK * D];
__device__ float g_q  [NTOK * D];
__device__ float g_k  [NTOK * D];
__device__ float g_v  [NTOK * D];
__device__ float g_att[NTOK * D];
__device__ float g_o  [NTOK * D];
__device__ float g_h1 [NTOK * D];
__device__ float g_mid[NTOK * DFF];
__device__ float g_f  [NTOK * D];
__device__ float g_h2 [NTOK * D];
// transposed weights ([N,K] K-major)
__device__ float g_WqT[D * D];
__device__ float g_WkT[D * D];
__device__ float g_WvT[D * D];
__device__ float g_WoT[D * D];
__device__ float g_W1T[DFF * D];
__device__ float g_W2T[D * DFF];
__device__ float g_WhT[VOCAB * D];

// ---------------------------------------------------------------------------
// tf32 helpers (plain compute_103-legal PTX only: mma.sync + cvt)
// ---------------------------------------------------------------------------
__device__ __forceinline__ uint32_t cvt_tf32(float f) {
    uint32_t r;
    asm("cvt.rna.tf32.f32 %0, %1;" : "=r"(r) : "f"(f));
    return r;
}

__device__ __forceinline__ void mma_tf32(float* d, const uint32_t* a, const uint32_t* b) {
    asm volatile(
        "mma.sync.aligned.m16n8k8.row.col.f32.tf32.tf32.f32 "
        "{%0,%1,%2,%3}, {%4,%5,%6,%7}, {%8,%9}, {%0,%1,%2,%3};"
        : "+f"(d[0]), "+f"(d[1]), "+f"(d[2]), "+f"(d[3])
        : "r"(a[0]), "r"(a[1]), "r"(a[2]), "r"(a[3]),
          "r"(b[0]), "r"(b[1]));
}

// ---------------------------------------------------------------------------
// Kernel: weight transpose  in[R][Cn] -> out[Cn][R]
// ---------------------------------------------------------------------------
__global__ void transpose_kernel(const float* __restrict__ in, float* __restrict__ out,
                                 int R, int Cn) {
    __shared__ float t[32][33];
    int bx = blockIdx.x * 32, by = blockIdx.y * 32;
    int x = bx + threadIdx.x;
    int y = by + threadIdx.y;
#pragma unroll
    for (int i = 0; i < 32; i += 8)
        t[threadIdx.y + i][threadIdx.x] = in[(size_t)(y + i) * Cn + x];
    __syncthreads();
    x = by + threadIdx.x;
    y = bx + threadIdx.y;
#pragma unroll
    for (int i = 0; i < 32; i += 8)
        out[(size_t)(y + i) * R + x] = t[threadIdx.x][threadIdx.y + i];
}

// ---------------------------------------------------------------------------
// Kernel: tf32 mma.sync GEMM  C[M,N] = A[M,K] @ Bt[N,K]^T + bias (+ReLU)
// CTA tile 256x128, BK=32, 256 threads (8 warps, 4x2), warp tile 64x64.
// SMEM: XOR-swizzled 16B groups, stride 32 floats. Register-prefetch pipeline.
// M%256==0, N%128==0, K%32==0 for all call sites.
// ---------------------------------------------------------------------------
#define GBM 256
#define GBN 128
#define GBK 32

__global__ __launch_bounds__(256, 1) void gemm_tc(
    const float* __restrict__ A, const float* __restrict__ Bt,
    const float* __restrict__ bias, float* __restrict__ C,
    int M, int N, int K, int relu)
{
    extern __shared__ uint32_t smem[];
    uint32_t* sA = smem;                 // GBM * 32
    uint32_t* sB = smem + GBM * 32;      // GBN * 32

    const int tid  = threadIdx.x;
    const int lane = tid & 31;
    const int wid  = tid >> 5;
    const int wm   = wid >> 1;           // 0..3  (M warps)
    const int wn   = wid & 1;            // 0..1  (N warps)
    const int bm   = blockIdx.y * GBM;
    const int bn   = blockIdx.x * GBN;

    float acc[4][8][4];
#pragma unroll
    for (int i = 0; i < 4; i++)
#pragma unroll
        for (int j = 0; j < 8; j++)
#pragma unroll
            for (int l = 0; l < 4; l++) acc[i][j][l] = 0.0f;

    float4 pa[8];
    float4 pb[4];
    const int nk = K >> 5;

    // ---- prefetch chunk 0 ----
#pragma unroll
    for (int t = 0; t < 8; t++) {
        int idx = t * 256 + tid;
        int r = idx >> 3, c4 = idx & 7;
        pa[t] = *(const float4*)(A + (size_t)(bm + r) * K + c4 * 4);
    }
#pragma unroll
    for (int t = 0; t < 4; t++) {
        int idx = t * 256 + tid;
        int r = idx >> 3, c4 = idx & 7;
        pb[t] = *(const float4*)(Bt + (size_t)(bn + r) * K + c4 * 4);
    }
    // ---- store chunk 0 ----
#pragma unroll
    for (int t = 0; t < 8; t++) {
        int idx = t * 256 + tid;
        int r = idx >> 3, c4 = idx & 7;
        uint4 v;
        v.x = cvt_tf32(pa[t].x); v.y = cvt_tf32(pa[t].y);
        v.z = cvt_tf32(pa[t].z); v.w = cvt_tf32(pa[t].w);
        *(uint4*)&sA[r * 32 + ((c4 ^ (r & 7)) << 2)] = v;
    }
#pragma unroll
    for (int t = 0; t < 4; t++) {
        int idx = t * 256 + tid;
        int r = idx >> 3, c4 = idx & 7;
        uint4 v;
        v.x = cvt_tf32(pb[t].x); v.y = cvt_tf32(pb[t].y);
        v.z = cvt_tf32(pb[t].z); v.w = cvt_tf32(pb[t].w);
        *(uint4*)&sB[r * 32 + ((c4 ^ (r & 7)) << 2)] = v;
    }
    __syncthreads();

    for (int chunk = 0; chunk < nk; chunk++) {
        // issue LDGs for next chunk early (latency overlapped with compute)
        if (chunk + 1 < nk) {
            const int kc = (chunk + 1) << 5;
#pragma unroll
            for (int t = 0; t < 8; t++) {
                int idx = t * 256 + tid;
                int r = idx >> 3, c4 = idx & 7;
                pa[t] = *(const float4*)(A + (size_t)(bm + r) * K + kc + c4 * 4);
            }
#pragma unroll
            for (int t = 0; t < 4; t++) {
                int idx = t * 256 + tid;
                int r = idx >> 3, c4 = idx & 7;
                pb[t] = *(const float4*)(Bt + (size_t)(bn + r) * K + kc + c4 * 4);
            }
        }

        // ---- compute 4 k-steps from SMEM ----
#pragma unroll
        for (int ks = 0; ks < 4; ks++) {
            uint32_t af[4][4];
#pragma unroll
            for (int mf = 0; mf < 4; mf++) {
                int r0 = wm * 64 + mf * 16 + (lane >> 2);
                int r1 = r0 + 8;
                int g0 = ks * 2, g1 = ks * 2 + 1;
                af[mf][0] = sA[r0 * 32 + ((g0 ^ (r0 & 7)) << 2) + (lane & 3)];
                af[mf][1] = sA[r1 * 32 + ((g0 ^ (r1 & 7)) << 2) + (lane & 3)];
                af[mf][2] = sA[r0 * 32 + ((g1 ^ (r0 & 7)) << 2) + (lane & 3)];
                af[mf][3] = sA[r1 * 32 + ((g1 ^ (r1 & 7)) << 2) + (lane & 3)];
            }
            uint32_t bf[8][2];
#pragma unroll
            for (int nf = 0; nf < 8; nf++) {
                int n0 = wn * 64 + nf * 8 + (lane >> 2);
                int g0 = ks * 2, g1 = ks * 2 + 1;
                bf[nf][0] = sB[n0 * 32 + ((g0 ^ (n0 & 7)) << 2) + (lane & 3)];
                bf[nf][1] = sB[n0 * 32 + ((g1 ^ (n0 & 7)) << 2) + (lane & 3)];
            }
#pragma unroll
            for (int mf = 0; mf < 4; mf++)
#pragma unroll
                for (int nf = 0; nf < 8; nf++)
                    mma_tf32(acc[mf][nf], af[mf], bf[nf]);
        }

        if (chunk + 1 < nk) {
            __syncthreads();   // everyone done reading current SMEM
#pragma unroll
            for (int t = 0; t < 8; t++) {
                int idx = t * 256 + tid;
                int r = idx >> 3, c4 = idx & 7;
                uint4 v;
                v.x = cvt_tf32(pa[t].x); v.y = cvt_tf32(pa[t].y);
                v.z = cvt_tf32(pa[t].z); v.w = cvt_tf32(pa[t].w);
                *(uint4*)&sA[r * 32 + ((c4 ^ (r & 7)) << 2)] = v;
            }
#pragma unroll
            for (int t = 0; t < 4; t++) {
                int idx = t * 256 + tid;
                int r = idx >> 3, c4 = idx & 7;
                uint4 v;
                v.x = cvt_tf32(pb[t].x); v.y = cvt_tf32(pb[t].y);
                v.z = cvt_tf32(pb[t].z); v.w = cvt_tf32(pb[t].w);
                *(uint4*)&sB[r * 32 + ((c4 ^ (r & 7)) << 2)] = v;
            }
            __syncthreads();
        }
    }

    // ---- epilogue: bias (+ReLU), direct float2 stores ----
#pragma unroll
    for (int mf = 0; mf < 4; mf++) {
        int row0 = bm + wm * 64 + mf * 16 + (lane >> 2);
#pragma unroll
        for (int nf = 0; nf < 8; nf++) {
            int col = bn + wn * 64 + nf * 8 + (lane & 3) * 2;
            float bx = bias[col], by = bias[col + 1];
            float2 v0, v1;
            v0.x = acc[mf][nf][0] + bx; v0.y = acc[mf][nf][1] + by;
            v1.x = acc[mf][nf][2] + bx; v1.y = acc[mf][nf][3] + by;
            if (relu) {
                v0.x = fmaxf(v0.x, 0.0f); v0.y = fmaxf(v0.y, 0.0f);
                v1.x = fmaxf(v1.x, 0.0f); v1.y = fmaxf(v1.y, 0.0f);
            }
            *(float2*)(C + (size_t)row0 * N + col)       = v0;
            *(float2*)(C + (size_t)(row0 + 8) * N + col) = v1;
        }
    }
}

// ---------------------------------------------------------------------------
// Kernel: embedding gather + 2D positional encoding
// ---------------------------------------------------------------------------
__global__ void embed_kernel(const int* __restrict__ x,
                             const float* __restrict__ tab,
                             const float* __restrict__ rowe,
                             const float* __restrict__ cole,
                             float* __restrict__ h) {
    int qi = blockIdx.x;
    int s  = qi & (SEQ - 1);
    int r  = s >> 5, c = s & 31;
    int tok = x[qi];
    int d = threadIdx.x * 4;

    float4 e = *(const float4*)&tab[(size_t)tok * D + d];
    float4 p;
    if (d < D / 2) p = *(const float4*)&rowe[r * (D / 2) + d];
    else           p = *(const float4*)&cole[c * (D / 2) + (d - D / 2)];
    e.x += p.x; e.y += p.y; e.z += p.z; e.w += p.w;
    *(float4*)&h[(size_t)qi * D + d] = e;
}

// ---------------------------------------------------------------------------
// Kernel: fused local-causal attention (<=181 keys per query)
// ---------------------------------------------------------------------------
__global__ void attn_kernel(const float* __restrict__ Q,
                            const float* __restrict__ K,
                            const float* __restrict__ V,
                            float* __restrict__ O) {
    int qi = blockIdx.x;
    int b = qi >> 10, s = qi & (SEQ - 1);
    int r = s >> 5, c = s & 31;
    int r0 = (r - WIN < 0) ? 0 : r - WIN;
    int c0 = (c - WIN < 0) ? 0 : c - WIN;
    int c1 = (c + WIN > 31) ? 31 : c + WIN;
    int wcols = c1 - c0 + 1;
    int nfull = r - r0;
    int nk = nfull * wcols + (c - c0 + 1);

    __shared__ float qv[D];
    __shared__ float sc[256];
    __shared__ int   kid[256];
    __shared__ float red[4];

    int tid = threadIdx.x;
    int lane = tid & 31, wid = tid >> 5;

    *(float4*)&qv[tid * 4] = *(const float4*)&Q[(size_t)qi * D + tid * 4];
    __syncthreads();

    const float scale = 0.044194173824159216f;
    const float* kbase = K + (size_t)b * SEQ * D;

    for (int j = wid; j < nk; j += 4) {
        int row, col;
        if (j < nfull * wcols) { row = r0 + j / wcols; col = c0 + j % wcols; }
        else                   { row = r;             col = c0 + (j - nfull * wcols); }
        int kk = row * 32 + col;
        const float* krow = kbase + (size_t)kk * D;
        float sum = 0.0f;
#pragma unroll
        for (int t = 0; t < D / 32; t++)
            sum = fmaf(qv[lane + 32 * t], krow[lane + 32 * t], sum);
#pragma unroll
        for (int off = 16; off; off >>= 1)
            sum += __shfl_xor_sync(0xffffffffu, sum, off);
        if (lane == 0) { sc[j] = sum * scale; kid[j] = kk; }
    }
    __syncthreads();

    float m = -1e30f;
    for (int j = tid; j < nk; j += 128) m = fmaxf(m, sc[j]);
#pragma unroll
    for (int off = 16; off; off >>= 1)
        m = fmaxf(m, __shfl_xor_sync(0xffffffffu, m, off));
    if (lane == 0) red[wid] = m;
    __syncthreads();
    m = fmaxf(fmaxf(red[0], red[1]), fmaxf(red[2], red[3]));

    float ssum = 0.0f;
    for (int j = tid; j < nk; j += 128) {
        float e = __expf(sc[j] - m);
        sc[j] = e;
        ssum += e;
    }
    __syncthreads();
#pragma unroll
    for (int off = 16; off; off >>= 1)
        ssum += __shfl_xor_sync(0xffffffffu, ssum, off);
    if (lane == 0) red[wid] = ssum;
    __syncthreads();
    float inv = 1.0f / (red[0] + red[1] + red[2] + red[3]);

    const float* vbase = V + (size_t)b * SEQ * D;
    int d = tid * 4;
    float4 acc = make_float4(0.f, 0.f, 0.f, 0.f);
    for (int j = 0; j < nk; j++) {
        float w = sc[j] * inv;
        float4 v = *(const float4*)&vbase[(size_t)kid[j] * D + d];
        acc.x = fmaf(w, v.x, acc.x);
        acc.y = fmaf(w, v.y, acc.y);
        acc.z = fmaf(w, v.z, acc.z);
        acc.w = fmaf(w, v.w, acc.w);
    }
    *(float4*)&O[(size_t)qi * D + d] = acc;
}

// ---------------------------------------------------------------------------
// Kernel: out = LayerNorm(X + Y) * g + b
// ---------------------------------------------------------------------------
__global__ void add_ln_kernel(const float* __restrict__ X,
                              const float* __restrict__ Y,
                              const float* __restrict__ g,
                              const float* __restrict__ beta,
                              float* __restrict__ out) {
    int row = blockIdx.x;
    int tid = threadIdx.x;
    int lane = tid & 31, wid = tid >> 5;
    __shared__ float reds[4], redq[4];

    int d = tid * 4;
    float4 xv = *(const float4*)&X[(size_t)row * D + d];
    float4 yv = *(const float4*)&Y[(size_t)row * D + d];
    xv.x += yv.x; xv.y += yv.y; xv.z += yv.z; xv.w += yv.w;

    float s  = xv.x + xv.y + xv.z + xv.w;
    float sq = xv.x * xv.x + xv.y * xv.y + xv.z * xv.z + xv.w * xv.w;
#pragma unroll
    for (int off = 16; off; off >>= 1) {
        s  += __shfl_xor_sync(0xffffffffu, s,  off);
        sq += __shfl_xor_sync(0xffffffffu, sq, off);
    }
    if (lane == 0) { reds[wid] = s; redq[wid] = sq; }
    __syncthreads();
    s  = reds[0] + reds[1] + reds[2] + reds[3];
    sq = redq[0] + redq[1] + redq[2] + redq[3];

    float mu  = s * (1.0f / D);
    float var = sq * (1.0f / D) - mu * mu;
    float rstd = rsqrtf(var + EPS);

    float4 gv = *(const float4*)&g[d];
    float4 bv = *(const float4*)&beta[d];
    float4 o;
    o.x = (xv.x - mu) * rstd * gv.x + bv.x;
    o.y = (xv.y - mu) * rstd * gv.y + bv.y;
    o.z = (xv.z - mu) * rstd * gv.z + bv.z;
    o.w = (xv.w - mu) * rstd * gv.w + bv.w;
    *(float4*)&out[(size_t)row * D + d] = o;
}

// ---------------------------------------------------------------------------
// Launch
// ---------------------------------------------------------------------------
extern "C" void kernel_launch(void* const* d_in, const int* in_sizes, int n_in,
                              void* d_out, int out_size) {
    const int*   x     = (const int*)  d_in[0];
    const float* tab   = (const float*)d_in[1];
    const float* rowe  = (const float*)d_in[2];
    const float* cole  = (const float*)d_in[3];
    const float* Wq    = (const float*)d_in[4];
    const float* bq    = (const float*)d_in[5];
    const float* Wk    = (const float*)d_in[6];
    const float* bk    = (const float*)d_in[7];
    const float* Wv    = (const float*)d_in[8];
    const float* bv    = (const float*)d_in[9];
    const float* Wo    = (const float*)d_in[10];
    const float* bo    = (const float*)d_in[11];
    const float* ln1g  = (const float*)d_in[12];
    const float* ln1b  = (const float*)d_in[13];
    const float* W1    = (const float*)d_in[14];
    const float* b1    = (const float*)d_in[15];
    const float* W2    = (const float*)d_in[16];
    const float* b2    = (const float*)d_in[17];
    const float* ln2g  = (const float*)d_in[18];
    const float* ln2b  = (const float*)d_in[19];
    const float* Wh    = (const float*)d_in[20];
    const float* bh    = (const float*)d_in[21];
    float* out = (float*)d_out;

    float *h0, *q, *k, *v, *att, *o, *h1, *mid, *f, *h2;
    float *WqT, *WkT, *WvT, *WoT, *W1T, *W2T, *WhT;
    cudaGetSymbolAddress((void**)&h0,  g_h0);
    cudaGetSymbolAddress((void**)&q,   g_q);
    cudaGetSymbolAddress((void**)&k,   g_k);
    cudaGetSymbolAddress((void**)&v,   g_v);
    cudaGetSymbolAddress((void**)&att, g_att);
    cudaGetSymbolAddress((void**)&o,   g_o);
    cudaGetSymbolAddress((void**)&h1,  g_h1);
    cudaGetSymbolAddress((void**)&mid, g_mid);
    cudaGetSymbolAddress((void**)&f,   g_f);
    cudaGetSymbolAddress((void**)&h2,  g_h2);
    cudaGetSymbolAddress((void**)&WqT, g_WqT);
    cudaGetSymbolAddress((void**)&WkT, g_WkT);
    cudaGetSymbolAddress((void**)&WvT, g_WvT);
    cudaGetSymbolAddress((void**)&WoT, g_WoT);
    cudaGetSymbolAddress((void**)&W1T, g_W1T);
    cudaGetSymbolAddress((void**)&W2T, g_W2T);
    cudaGetSymbolAddress((void**)&WhT, g_WhT);

    const int GEMM_SMEM = (GBM * 32 + GBN * 32) * 4;  // 49152 bytes
    static int attr_set = 0;
    if (!attr_set) {
        cudaFuncSetAttribute(gemm_tc, cudaFuncAttributeMaxDynamicSharedMemorySize, GEMM_SMEM);
        attr_set = 1;
    }

    dim3 tb(32, 8);
    // weight transposes: [K,N] -> [N,K]
    transpose_kernel<<<dim3(D / 32,     D / 32),   tb>>>(Wq, WqT, D,   D);
    transpose_kernel<<<dim3(D / 32,     D / 32),   tb>>>(Wk, WkT, D,   D);
    transpose_kernel<<<dim3(D / 32,     D / 32),   tb>>>(Wv, WvT, D,   D);
    transpose_kernel<<<dim3(D / 32,     D / 32),   tb>>>(Wo, WoT, D,   D);
    transpose_kernel<<<dim3(DFF / 32,   D / 32),   tb>>>(W1, W1T, D,   DFF);
    transpose_kernel<<<dim3(D / 32,     DFF / 32), tb>>>(W2, W2T, DFF, D);
    transpose_kernel<<<dim3(VOCAB / 32, D / 32),   tb>>>(Wh, WhT, D,   VOCAB);

    // 1. embedding + pos
    embed_kernel<<<NTOK, 128>>>(x, tab, rowe, cole, h0);

    // 2. Q,K,V projections (tf32 mma.sync tensor core)
    gemm_tc<<<dim3(D / GBN, NTOK / GBM), 256, GEMM_SMEM>>>(h0, WqT, bq, q, NTOK, D, D, 0);
    gemm_tc<<<dim3(D / GBN, NTOK / GBM), 256, GEMM_SMEM>>>(h0, WkT, bk, k, NTOK, D, D, 0);
    gemm_tc<<<dim3(D / GBN, NTOK / GBM), 256, GEMM_SMEM>>>(h0, WvT, bv, v, NTOK, D, D, 0);

    // 3. fused local-causal attention
    attn_kernel<<<NTOK, 128>>>(q, k, v, att);

    // 4. output projection
    gemm_tc<<<dim3(D / GBN, NTOK / GBM), 256, GEMM_SMEM>>>(att, WoT, bo, o, NTOK, D, D, 0);

    // 5. residual + LN1
    add_ln_kernel<<<NTOK, 128>>>(h0, o, ln1g, ln1b, h1);

    // 6. FFN
    gemm_tc<<<dim3(DFF / GBN, NTOK / GBM), 256, GEMM_SMEM>>>(h1, W1T, b1, mid, NTOK, DFF, D, 1);
    gemm_tc<<<dim3(D / GBN, NTOK / GBM), 256, GEMM_SMEM>>>(mid, W2T, b2, f, NTOK, D, DFF, 0);

    // 7. residual + LN2
    add_ln_kernel<<<NTOK, 128>>>(h1, f, ln2g, ln2b, h2);

    // 8. vocab head -> d_out
    gemm_tc<<<dim3(VOCAB / GBN, NTOK / GBM), 256, GEMM_SMEM>>>(h2, WhT, bh, out, NTOK, VOCAB, D, 0);
}

// round 6
// speedup vs baseline: 5.5872x; 1.2585x over previous
#include <cuda_runtime.h>
#include <cuda_bf16.h>
#include <math.h>
#include <cstdint>

// ---------------------------------------------------------------------------
// Problem constants
// ---------------------------------------------------------------------------
#define B 8
#define SEQ 1024
#define WIN 9
#define D 512
#define DFF 1024
#define VOCAB 16384
#define NTOK (B * SEQ)   // 8192
#define EPS 1e-5f

// ---------------------------------------------------------------------------
// Scratch buffers (device globals: no allocation allowed)
// ---------------------------------------------------------------------------
__device__ float g_h0 [NTOK * D];
__device__ float g_q  [NTOK * D];
__device__ float g_k  [NTOK * D];
__device__ float g_v  [NTOK * D];
__device__ float g_att[NTOK * D];
__device__ float g_o  [NTOK * D];
__device__ float g_h1 [NTOK * D];
__device__ float g_mid[NTOK * DFF];
__device__ float g_f  [NTOK * D];
__device__ float g_h2 [NTOK * D];
// transposed weights ([N,K] K-major, values pre-rounded to tf32)
__device__ float g_WqT[D * D];
__device__ float g_WkT[D * D];
__device__ float g_WvT[D * D];
__device__ float g_WoT[D * D];
__device__ float g_W1T[DFF * D];
__device__ float g_W2T[D * DFF];
__device__ float g_WhT[VOCAB * D];

// ---------------------------------------------------------------------------
// tf32 / cp.async helpers (all plain compute_103-legal PTX)
// ---------------------------------------------------------------------------
__device__ __forceinline__ uint32_t cvt_tf32(float f) {
    uint32_t r;
    asm("cvt.rna.tf32.f32 %0, %1;" : "=r"(r) : "f"(f));
    return r;
}
__device__ __forceinline__ float round_tf32(float f) {
    return __uint_as_float(cvt_tf32(f));
}
__device__ __forceinline__ uint32_t smem_to_u32(const void* p) {
    uint32_t a;
    asm("{ .reg .u64 t; cvta.to.shared.u64 t, %1; cvt.u32.u64 %0, t; }" : "=r"(a) : "l"(p));
    return a;
}
__device__ __forceinline__ void cp_async16(uint32_t saddr, const void* gptr) {
    asm volatile("cp.async.cg.shared.global [%0], [%1], 16;" :: "r"(saddr), "l"(gptr));
}
#define CP_COMMIT()  asm volatile("cp.async.commit_group;" ::: "memory")
#define CP_WAIT(n)   asm volatile("cp.async.wait_group %0;" :: "n"(n) : "memory")

__device__ __forceinline__ void mma_tf32(float* d, const uint32_t* a, const uint32_t* b) {
    asm volatile(
        "mma.sync.aligned.m16n8k8.row.col.f32.tf32.tf32.f32 "
        "{%0,%1,%2,%3}, {%4,%5,%6,%7}, {%8,%9}, {%0,%1,%2,%3};"
        : "+f"(d[0]), "+f"(d[1]), "+f"(d[2]), "+f"(d[3])
        : "r"(a[0]), "r"(a[1]), "r"(a[2]), "r"(a[3]),
          "r"(b[0]), "r"(b[1]));
}

// ---------------------------------------------------------------------------
// Kernel: weight transpose + tf32 round   in[R][Cn] -> out[Cn][R]
// ---------------------------------------------------------------------------
__global__ void transpose_kernel(const float* __restrict__ in, float* __restrict__ out,
                                 int R, int Cn) {
    __shared__ float t[32][33];
    int bx = blockIdx.x * 32, by = blockIdx.y * 32;
    int x = bx + threadIdx.x;
    int y = by + threadIdx.y;
#pragma unroll
    for (int i = 0; i < 32; i += 8)
        t[threadIdx.y + i][threadIdx.x] = in[(size_t)(y + i) * Cn + x];
    __syncthreads();
    x = by + threadIdx.x;
    y = bx + threadIdx.y;
#pragma unroll
    for (int i = 0; i < 32; i += 8)
        out[(size_t)(y + i) * R + x] = round_tf32(t[threadIdx.x][threadIdx.y + i]);
}

// ---------------------------------------------------------------------------
// Kernel: tf32 mma.sync GEMM  C[M,N] = A[M,K] @ Bt[N,K]^T + bias (+ReLU)(+tf32 round)
// CTA tile 256x128, BK=32, 256 threads (8 warps 4x2), warp tile 64x64.
// 4-stage cp.async pipeline into XOR-swizzled SMEM. Inputs must already be
// tf32-rounded fp32 (producers round at store time).
// ---------------------------------------------------------------------------
#define GBM 256
#define GBN 128
#define GBK 32
#define STAGES 4
#define STAGE_AU (GBM * 32)          // uint32s per A stage
#define STAGE_BU (GBN * 32)          // uint32s per B stage

__global__ __launch_bounds__(256, 1) void gemm_tc(
    const float* __restrict__ A, const float* __restrict__ Bt,
    const float* __restrict__ bias, float* __restrict__ C,
    int M, int N, int K, int relu, int round_out)
{
    extern __shared__ uint32_t smem[];
    uint32_t* sAbuf = smem;                        // STAGES * STAGE_AU
    uint32_t* sBbuf = smem + STAGES * STAGE_AU;    // STAGES * STAGE_BU
    const uint32_t sA_u32 = smem_to_u32(sAbuf);
    const uint32_t sB_u32 = smem_to_u32(sBbuf);

    const int tid  = threadIdx.x;
    const int lane = tid & 31;
    const int wid  = tid >> 5;
    const int wm   = wid >> 1;           // 0..3
    const int wn   = wid & 1;            // 0..1
    const int bm   = blockIdx.y * GBM;
    const int bn   = blockIdx.x * GBN;
    const int nk   = K >> 5;

    // per-thread copy coordinates (A: 8 x 16B, B: 4 x 16B per chunk)
    int ar[8], ac[8]; uint32_t aso[8];
#pragma unroll
    for (int t = 0; t < 8; t++) {
        int idx = t * 256 + tid;
        ar[t] = idx >> 3; ac[t] = idx & 7;
        aso[t] = (uint32_t)(ar[t] * 32 + ((ac[t] ^ (ar[t] & 7)) << 2)) * 4u;
    }
    int br[4], bc[4]; uint32_t bso[4];
#pragma unroll
    for (int t = 0; t < 4; t++) {
        int idx = t * 256 + tid;
        br[t] = idx >> 3; bc[t] = idx & 7;
        bso[t] = (uint32_t)(br[t] * 32 + ((bc[t] ^ (br[t] & 7)) << 2)) * 4u;
    }

    float acc[4][8][4];
#pragma unroll
    for (int i = 0; i < 4; i++)
#pragma unroll
        for (int j = 0; j < 8; j++)
#pragma unroll
            for (int l = 0; l < 4; l++) acc[i][j][l] = 0.0f;

#define LOAD_STAGE(chunk, stage) do { \
    const int _kc = (chunk) << 5; \
    const uint32_t _sa = sA_u32 + (uint32_t)(stage) * (STAGE_AU * 4); \
    const uint32_t _sb = sB_u32 + (uint32_t)(stage) * (STAGE_BU * 4); \
    _Pragma("unroll") \
    for (int _t = 0; _t < 8; _t++) \
        cp_async16(_sa + aso[_t], A + (size_t)(bm + ar[_t]) * K + _kc + ac[_t] * 4); \
    _Pragma("unroll") \
    for (int _t = 0; _t < 4; _t++) \
        cp_async16(_sb + bso[_t], Bt + (size_t)(bn + br[_t]) * K + _kc + bc[_t] * 4); \
    CP_COMMIT(); \
} while (0)

    // prologue: stages 0..2   (nk >= 16 at every call site)
    LOAD_STAGE(0, 0);
    LOAD_STAGE(1, 1);
    LOAD_STAGE(2, 2);

    for (int chunk = 0; chunk < nk; chunk++) {
        CP_WAIT(STAGES - 2);
        __syncthreads();   // chunk's stage complete everywhere; prev compute done

        if (chunk + STAGES - 1 < nk) {
            LOAD_STAGE(chunk + STAGES - 1, (chunk + STAGES - 1) & (STAGES - 1));
        } else {
            CP_COMMIT();   // keep group arithmetic uniform
        }

        const uint32_t* sA = sAbuf + (chunk & (STAGES - 1)) * STAGE_AU;
        const uint32_t* sB = sBbuf + (chunk & (STAGES - 1)) * STAGE_BU;

#pragma unroll
        for (int ks = 0; ks < 4; ks++) {
            uint32_t af[4][4];
#pragma unroll
            for (int mf = 0; mf < 4; mf++) {
                int r0 = wm * 64 + mf * 16 + (lane >> 2);
                int r1 = r0 + 8;
                int g0 = ks * 2, g1 = ks * 2 + 1;
                af[mf][0] = sA[r0 * 32 + ((g0 ^ (r0 & 7)) << 2) + (lane & 3)];
                af[mf][1] = sA[r1 * 32 + ((g0 ^ (r1 & 7)) << 2) + (lane & 3)];
                af[mf][2] = sA[r0 * 32 + ((g1 ^ (r0 & 7)) << 2) + (lane & 3)];
                af[mf][3] = sA[r1 * 32 + ((g1 ^ (r1 & 7)) << 2) + (lane & 3)];
            }
            uint32_t bf[8][2];
#pragma unroll
            for (int nf = 0; nf < 8; nf++) {
                int n0 = wn * 64 + nf * 8 + (lane >> 2);
                int g0 = ks * 2, g1 = ks * 2 + 1;
                bf[nf][0] = sB[n0 * 32 + ((g0 ^ (n0 & 7)) << 2) + (lane & 3)];
                bf[nf][1] = sB[n0 * 32 + ((g1 ^ (n0 & 7)) << 2) + (lane & 3)];
            }
#pragma unroll
            for (int mf = 0; mf < 4; mf++)
#pragma unroll
                for (int nf = 0; nf < 8; nf++)
                    mma_tf32(acc[mf][nf], af[mf], bf[nf]);
        }
    }

    // ---- epilogue ----
#pragma unroll
    for (int mf = 0; mf < 4; mf++) {
        int row0 = bm + wm * 64 + mf * 16 + (lane >> 2);
#pragma unroll
        for (int nf = 0; nf < 8; nf++) {
            int col = bn + wn * 64 + nf * 8 + (lane & 3) * 2;
            float bx = bias[col], by = bias[col + 1];
            float2 v0, v1;
            v0.x = acc[mf][nf][0] + bx; v0.y = acc[mf][nf][1] + by;
            v1.x = acc[mf][nf][2] + bx; v1.y = acc[mf][nf][3] + by;
            if (relu) {
                v0.x = fmaxf(v0.x, 0.0f); v0.y = fmaxf(v0.y, 0.0f);
                v1.x = fmaxf(v1.x, 0.0f); v1.y = fmaxf(v1.y, 0.0f);
            }
            if (round_out) {
                v0.x = round_tf32(v0.x); v0.y = round_tf32(v0.y);
                v1.x = round_tf32(v1.x); v1.y = round_tf32(v1.y);
            }
            *(float2*)(C + (size_t)row0 * N + col)       = v0;
            *(float2*)(C + (size_t)(row0 + 8) * N + col) = v1;
        }
    }
}

// ---------------------------------------------------------------------------
// Kernel: embedding gather + 2D positional encoding (output tf32-rounded)
// ---------------------------------------------------------------------------
__global__ void embed_kernel(const int* __restrict__ x,
                             const float* __restrict__ tab,
                             const float* __restrict__ rowe,
                             const float* __restrict__ cole,
                             float* __restrict__ h) {
    int qi = blockIdx.x;
    int s  = qi & (SEQ - 1);
    int r  = s >> 5, c = s & 31;
    int tok = x[qi];
    int d = threadIdx.x * 4;

    float4 e = *(const float4*)&tab[(size_t)tok * D + d];
    float4 p;
    if (d < D / 2) p = *(const float4*)&rowe[r * (D / 2) + d];
    else           p = *(const float4*)&cole[c * (D / 2) + (d - D / 2)];
    e.x = round_tf32(e.x + p.x); e.y = round_tf32(e.y + p.y);
    e.z = round_tf32(e.z + p.z); e.w = round_tf32(e.w + p.w);
    *(float4*)&h[(size_t)qi * D + d] = e;
}

// ---------------------------------------------------------------------------
// Kernel: fused local-causal attention (<=181 keys; output tf32-rounded)
// ---------------------------------------------------------------------------
__global__ void attn_kernel(const float* __restrict__ Q,
                            const float* __restrict__ K,
                            const float* __restrict__ V,
                            float* __restrict__ O) {
    int qi = blockIdx.x;
    int b = qi >> 10, s = qi & (SEQ - 1);
    int r = s >> 5, c = s & 31;
    int r0 = (r - WIN < 0) ? 0 : r - WIN;
    int c0 = (c - WIN < 0) ? 0 : c - WIN;
    int c1 = (c + WIN > 31) ? 31 : c + WIN;
    int wcols = c1 - c0 + 1;
    int nfull = r - r0;
    int nk = nfull * wcols + (c - c0 + 1);

    __shared__ float qv[D];
    __shared__ float sc[256];
    __shared__ int   kid[256];
    __shared__ float red[4];

    int tid = threadIdx.x;
    int lane = tid & 31, wid = tid >> 5;

    *(float4*)&qv[tid * 4] = *(const float4*)&Q[(size_t)qi * D + tid * 4];
    __syncthreads();

    const float scale = 0.044194173824159216f;
    const float* kbase = K + (size_t)b * SEQ * D;

    for (int j = wid; j < nk; j += 4) {
        int row, col;
        if (j < nfull * wcols) { row = r0 + j / wcols; col = c0 + j % wcols; }
        else                   { row = r;             col = c0 + (j - nfull * wcols); }
        int kk = row * 32 + col;
        const float* krow = kbase + (size_t)kk * D;
        float sum = 0.0f;
#pragma unroll
        for (int t = 0; t < D / 32; t++)
            sum = fmaf(qv[lane + 32 * t], krow[lane + 32 * t], sum);
#pragma unroll
        for (int off = 16; off; off >>= 1)
            sum += __shfl_xor_sync(0xffffffffu, sum, off);
        if (lane == 0) { sc[j] = sum * scale; kid[j] = kk; }
    }
    __syncthreads();

    float m = -1e30f;
    for (int j = tid; j < nk; j += 128) m = fmaxf(m, sc[j]);
#pragma unroll
    for (int off = 16; off; off >>= 1)
        m = fmaxf(m, __shfl_xor_sync(0xffffffffu, m, off));
    if (lane == 0) red[wid] = m;
    __syncthreads();
    m = fmaxf(fmaxf(red[0], red[1]), fmaxf(red[2], red[3]));

    float ssum = 0.0f;
    for (int j = tid; j < nk; j += 128) {
        float e = __expf(sc[j] - m);
        sc[j] = e;
        ssum += e;
    }
    __syncthreads();
#pragma unroll
    for (int off = 16; off; off >>= 1)
        ssum += __shfl_xor_sync(0xffffffffu, ssum, off);
    if (lane == 0) red[wid] = ssum;
    __syncthreads();
    float inv = 1.0f / (red[0] + red[1] + red[2] + red[3]);

    const float* vbase = V + (size_t)b * SEQ * D;
    int d = tid * 4;
    float4 acc = make_float4(0.f, 0.f, 0.f, 0.f);
    for (int j = 0; j < nk; j++) {
        float w = sc[j] * inv;
        float4 v = *(const float4*)&vbase[(size_t)kid[j] * D + d];
        acc.x = fmaf(w, v.x, acc.x);
        acc.y = fmaf(w, v.y, acc.y);
        acc.z = fmaf(w, v.z, acc.z);
        acc.w = fmaf(w, v.w, acc.w);
    }
    acc.x = round_tf32(acc.x); acc.y = round_tf32(acc.y);
    acc.z = round_tf32(acc.z); acc.w = round_tf32(acc.w);
    *(float4*)&O[(size_t)qi * D + d] = acc;
}

// ---------------------------------------------------------------------------
// Kernel: out = LayerNorm(X + Y) * g + b   (output tf32-rounded)
// ---------------------------------------------------------------------------
__global__ void add_ln_kernel(const float* __restrict__ X,
                              const float* __restrict__ Y,
                              const float* __restrict__ g,
                              const float* __restrict__ beta,
                              float* __restrict__ out) {
    int row = blockIdx.x;
    int tid = threadIdx.x;
    int lane = tid & 31, wid = tid >> 5;
    __shared__ float reds[4], redq[4];

    int d = tid * 4;
    float4 xv = *(const float4*)&X[(size_t)row * D + d];
    float4 yv = *(const float4*)&Y[(size_t)row * D + d];
    xv.x += yv.x; xv.y += yv.y; xv.z += yv.z; xv.w += yv.w;

    float s  = xv.x + xv.y + xv.z + xv.w;
    float sq = xv.x * xv.x + xv.y * xv.y + xv.z * xv.z + xv.w * xv.w;
#pragma unroll
    for (int off = 16; off; off >>= 1) {
        s  += __shfl_xor_sync(0xffffffffu, s,  off);
        sq += __shfl_xor_sync(0xffffffffu, sq, off);
    }
    if (lane == 0) { reds[wid] = s; redq[wid] = sq; }
    __syncthreads();
    s  = reds[0] + reds[1] + reds[2] + reds[3];
    sq = redq[0] + redq[1] + redq[2] + redq[3];

    float mu  = s * (1.0f / D);
    float var = sq * (1.0f / D) - mu * mu;
    float rstd = rsqrtf(var + EPS);

    float4 gv = *(const float4*)&g[d];
    float4 bv = *(const float4*)&beta[d];
    float4 o;
    o.x = round_tf32((xv.x - mu) * rstd * gv.x + bv.x);
    o.y = round_tf32((xv.y - mu) * rstd * gv.y + bv.y);
    o.z = round_tf32((xv.z - mu) * rstd * gv.z + bv.z);
    o.w = round_tf32((xv.w - mu) * rstd * gv.w + bv.w);
    *(float4*)&out[(size_t)row * D + d] = o;
}

// ---------------------------------------------------------------------------
// Launch
// ---------------------------------------------------------------------------
extern "C" void kernel_launch(void* const* d_in, const int* in_sizes, int n_in,
                              void* d_out, int out_size) {
    const int*   x     = (const int*)  d_in[0];
    const float* tab   = (const float*)d_in[1];
    const float* rowe  = (const float*)d_in[2];
    const float* cole  = (const float*)d_in[3];
    const float* Wq    = (const float*)d_in[4];
    const float* bq    = (const float*)d_in[5];
    const float* Wk    = (const float*)d_in[6];
    const float* bk    = (const float*)d_in[7];
    const float* Wv    = (const float*)d_in[8];
    const float* bv    = (const float*)d_in[9];
    const float* Wo    = (const float*)d_in[10];
    const float* bo    = (const float*)d_in[11];
    const float* ln1g  = (const float*)d_in[12];
    const float* ln1b  = (const float*)d_in[13];
    const float* W1    = (const float*)d_in[14];
    const float* b1    = (const float*)d_in[15];
    const float* W2    = (const float*)d_in[16];
    const float* b2    = (const float*)d_in[17];
    const float* ln2g  = (const float*)d_in[18];
    const float* ln2b  = (const float*)d_in[19];
    const float* Wh    = (const float*)d_in[20];
    const float* bh    = (const float*)d_in[21];
    float* out = (float*)d_out;

    float *h0, *q, *k, *v, *att, *o, *h1, *mid, *f, *h2;
    float *WqT, *WkT, *WvT, *WoT, *W1T, *W2T, *WhT;
    cudaGetSymbolAddress((void**)&h0,  g_h0);
    cudaGetSymbolAddress((void**)&q,   g_q);
    cudaGetSymbolAddress((void**)&k,   g_k);
    cudaGetSymbolAddress((void**)&v,   g_v);
    cudaGetSymbolAddress((void**)&att, g_att);
    cudaGetSymbolAddress((void**)&o,   g_o);
    cudaGetSymbolAddress((void**)&h1,  g_h1);
    cudaGetSymbolAddress((void**)&mid, g_mid);
    cudaGetSymbolAddress((void**)&f,   g_f);
    cudaGetSymbolAddress((void**)&h2,  g_h2);
    cudaGetSymbolAddress((void**)&WqT, g_WqT);
    cudaGetSymbolAddress((void**)&WkT, g_WkT);
    cudaGetSymbolAddress((void**)&WvT, g_WvT);
    cudaGetSymbolAddress((void**)&WoT, g_WoT);
    cudaGetSymbolAddress((void**)&W1T, g_W1T);
    cudaGetSymbolAddress((void**)&W2T, g_W2T);
    cudaGetSymbolAddress((void**)&WhT, g_WhT);

    const int GEMM_SMEM = STAGES * (STAGE_AU + STAGE_BU) * 4;  // 196608 bytes
    static int attr_set = 0;
    if (!attr_set) {
        cudaFuncSetAttribute(gemm_tc, cudaFuncAttributeMaxDynamicSharedMemorySize, GEMM_SMEM);
        attr_set = 1;
    }

    dim3 tb(32, 8);
    // launches 1-5 (ncu captures launch #6 = gemm_tc below)
    transpose_kernel<<<dim3(D / 32,     D / 32),   tb>>>(Wq, WqT, D,   D);
    transpose_kernel<<<dim3(D / 32,     D / 32),   tb>>>(Wk, WkT, D,   D);
    transpose_kernel<<<dim3(D / 32,     D / 32),   tb>>>(Wv, WvT, D,   D);
    transpose_kernel<<<dim3(DFF / 32,   D / 32),   tb>>>(W1, W1T, D,   DFF);
    embed_kernel<<<NTOK, 128>>>(x, tab, rowe, cole, h0);

    // launch #6: profiled GEMM
    gemm_tc<<<dim3(D / GBN, NTOK / GBM), 256, GEMM_SMEM>>>(h0, WqT, bq, q, NTOK, D, D, 0, 0);
    gemm_tc<<<dim3(D / GBN, NTOK / GBM), 256, GEMM_SMEM>>>(h0, WkT, bk, k, NTOK, D, D, 0, 0);
    gemm_tc<<<dim3(D / GBN, NTOK / GBM), 256, GEMM_SMEM>>>(h0, WvT, bv, v, NTOK, D, D, 0, 0);

    // remaining weight transposes (overlap-friendly, before their consumers)
    transpose_kernel<<<dim3(D / 32,     D / 32),   tb>>>(Wo, WoT, D,   D);
    transpose_kernel<<<dim3(D / 32,     DFF / 32), tb>>>(W2, W2T, DFF, D);
    transpose_kernel<<<dim3(VOCAB / 32, D / 32),   tb>>>(Wh, WhT, D,   VOCAB);

    // fused local-causal attention
    attn_kernel<<<NTOK, 128>>>(q, k, v, att);

    // output projection
    gemm_tc<<<dim3(D / GBN, NTOK / GBM), 256, GEMM_SMEM>>>(att, WoT, bo, o, NTOK, D, D, 0, 0);

    // residual + LN1
    add_ln_kernel<<<NTOK, 128>>>(h0, o, ln1g, ln1b, h1);

    // FFN (mid output tf32-rounded: consumed by FFN2 GEMM)
    gemm_tc<<<dim3(DFF / GBN, NTOK / GBM), 256, GEMM_SMEM>>>(h1, W1T, b1, mid, NTOK, DFF, D, 1, 1);
    gemm_tc<<<dim3(D / GBN, NTOK / GBM), 256, GEMM_SMEM>>>(mid, W2T, b2, f, NTOK, D, DFF, 0, 0);

    // residual + LN2
    add_ln_kernel<<<NTOK, 128>>>(h1, f, ln2g, ln2b, h2);

    // vocab head -> d_out
    gemm_tc<<<dim3(VOCAB / GBN, NTOK / GBM), 256, GEMM_SMEM>>>(h2, WhT, bh, out, NTOK, VOCAB, D, 0, 0);
}